// round 1
// baseline (speedup 1.0000x reference)
#include <cuda_runtime.h>
#include <cuda_bf16.h>

#define D 8192
#define BATCH 4096

// Scratch for the computed weight row (allocation-free rule: __device__ global).
__device__ float d_w[D];

// Kernel 1: w[j] = s1[0] * s2[j] * FWHT(g_mu + softplus(g_rho)*eps)[j]
// Single block, 1024 threads, full 8192-pt FWHT in shared memory.
__global__ __launch_bounds__(1024, 1)
void fwht_kernel(const float* __restrict__ s1,
                 const float* __restrict__ s2,
                 const float* __restrict__ g_mu,
                 const float* __restrict__ g_rho,
                 const float* __restrict__ eps) {
    __shared__ float sh[D];
    const int tid = threadIdx.x;

    // g_tilde = g_mu + softplus(g_rho) * eps  (numerically stable softplus)
    #pragma unroll
    for (int i = 0; i < D / 1024; i++) {
        int j = tid + i * 1024;
        float r  = g_rho[j];
        float sp = fmaxf(r, 0.0f) + log1pf(expf(-fabsf(r)));
        sh[j] = g_mu[j] + sp * eps[j];
    }
    __syncthreads();

    // 13 butterfly stages (unnormalized Sylvester-order FWHT, matches reference)
    for (int h = 1; h < D; h <<= 1) {
        #pragma unroll
        for (int i = 0; i < (D / 2) / 1024; i++) {
            int idx = tid + i * 1024;                       // butterfly id 0..4095
            int a = ((idx & ~(h - 1)) << 1) | (idx & (h - 1));
            int b = a + h;
            float va = sh[a], vb = sh[b];
            sh[a] = va + vb;
            sh[b] = va - vb;
        }
        __syncthreads();
    }

    float s10 = s1[0];
    #pragma unroll
    for (int i = 0; i < D / 1024; i++) {
        int j = tid + i * 1024;
        d_w[j] = s10 * s2[j] * sh[j];
    }
}

// Kernel 2: out[b][j] = x[b] * w[j]   (128 MiB streaming store)
// grid (8, 256) x 256 threads. blockIdx.x picks a 1024-float column chunk;
// each thread owns one float4 of w in registers and streams 16 rows.
#define ROWS_PER_BLOCK 16

__global__ __launch_bounds__(256)
void outer_kernel(const float* __restrict__ x, float* __restrict__ out) {
    const int jbase = blockIdx.x * 1024 + threadIdx.x * 4;
    const float4 w4 = *reinterpret_cast<const float4*>(&d_w[jbase]);
    const int b0 = blockIdx.y * ROWS_PER_BLOCK;

    float xs[ROWS_PER_BLOCK];
    #pragma unroll
    for (int r = 0; r < ROWS_PER_BLOCK; r++)
        xs[r] = __ldg(&x[b0 + r]);               // broadcast, L1-resident

    #pragma unroll
    for (int r = 0; r < ROWS_PER_BLOCK; r++) {
        float4 o;
        o.x = xs[r] * w4.x;
        o.y = xs[r] * w4.y;
        o.z = xs[r] * w4.z;
        o.w = xs[r] * w4.w;
        // Streaming store: output (134MB) exceeds L2 and is never re-read.
        __stcs(reinterpret_cast<float4*>(out + (size_t)(b0 + r) * D + jbase), o);
    }
}

extern "C" void kernel_launch(void* const* d_in, const int* in_sizes, int n_in,
                              void* d_out, int out_size) {
    const float* x     = (const float*)d_in[0];  // (4096, 1)
    const float* s1    = (const float*)d_in[1];  // (8192,)
    const float* s2    = (const float*)d_in[2];  // (8192,)
    const float* g_mu  = (const float*)d_in[3];  // (8192,)
    const float* g_rho = (const float*)d_in[4];  // (8192,)
    const float* eps   = (const float*)d_in[5];  // (8192,)
    float* out = (float*)d_out;                  // (4096, 8192) f32

    fwht_kernel<<<1, 1024>>>(s1, s2, g_mu, g_rho, eps);

    dim3 grid(D / 1024, BATCH / ROWS_PER_BLOCK);  // (8, 256)
    outer_kernel<<<grid, 256>>>(x, out);
}

// round 2
// speedup vs baseline: 1.0195x; 1.0195x over previous
#include <cuda_runtime.h>
#include <cuda_bf16.h>

#define D 8192
#define BATCH 4096

// Scratch for the computed weight row (allocation-free rule: __device__ global).
__device__ float d_w[D];

// ---------------------------------------------------------------------------
// Kernel 1: w[j] = s1[0] * s2[j] * FWHT(g_mu + softplus(g_rho)*eps)[j]
// Single block, 1024 threads, 8 elements/thread.
//   Phase 1: bits 0-2 in registers, bits 3-7 via warp shuffles (1 instr/stage/reg)
//   Transpose through smem with XOR swizzle (conflict-free store AND load)
//   Phase 2: bits 8-12 via warp shuffles
// One __syncthreads() total. Hadamard stages commute, so any bit order is valid.
// ---------------------------------------------------------------------------
__global__ __launch_bounds__(1024, 1)
void fwht_kernel(const float* __restrict__ s1,
                 const float* __restrict__ s2,
                 const float* __restrict__ g_mu,
                 const float* __restrict__ g_rho,
                 const float* __restrict__ eps) {
#if __CUDA_ARCH__ >= 900
    // Let the dependent outer_kernel start its prologue immediately.
    cudaTriggerProgrammaticLaunchCompletion();
#endif
    __shared__ float sh[D];
    const int t    = threadIdx.x;
    const int lane = t & 31;
    const int w    = t >> 5;

    float r[8];
    {
        const int base = t * 8;
        float mu[8], rh[8], ep[8];
        *(float4*)&mu[0] = *(const float4*)(g_mu  + base);
        *(float4*)&mu[4] = *(const float4*)(g_mu  + base + 4);
        *(float4*)&rh[0] = *(const float4*)(g_rho + base);
        *(float4*)&rh[4] = *(const float4*)(g_rho + base + 4);
        *(float4*)&ep[0] = *(const float4*)(eps   + base);
        *(float4*)&ep[4] = *(const float4*)(eps   + base + 4);
        #pragma unroll
        for (int k = 0; k < 8; k++) {
            float v  = rh[k];
            float sp = fmaxf(v, 0.0f) + __logf(1.0f + __expf(-fabsf(v)));
            r[k] = fmaf(sp, ep[k], mu[k]);
        }
    }

    // bits 0-2: butterflies among the 8 registers (element idx = 8t + k)
    #pragma unroll
    for (int s = 1; s < 8; s <<= 1) {
        #pragma unroll
        for (int k = 0; k < 8; k++) {
            if (!(k & s)) {
                float a = r[k], b = r[k | s];
                r[k]     = a + b;
                r[k | s] = a - b;
            }
        }
    }

    // bits 3-7 (strides 8..128): idx bit (3+s) == lane bit s -> shfl.xor
    #pragma unroll
    for (int m = 1; m <= 16; m <<= 1) {
        const float sgn = (lane & m) ? -1.0f : 1.0f;
        #pragma unroll
        for (int k = 0; k < 8; k++) {
            float o = __shfl_xor_sync(0xffffffffu, r[k], m);
            r[k] = fmaf(sgn, r[k], o);   // bit0 lane: r+o = a+b ; bit1 lane: -b+a
        }
    }

    // Swizzled transpose: addr(idx) = (idx&255)*32 + ((idx>>8) ^ ((idx>>3)&31)).
    // Store (idx = 8t+k): addr = (lane*8+k)*32 + (w ^ lane)  -> banks w^lane: distinct per warp
    {
        const int swz = w ^ lane;
        #pragma unroll
        for (int k = 0; k < 8; k++)
            sh[(lane * 8 + k) * 32 + swz] = r[k];
    }
    __syncthreads();

    // Load (idx = lane*256 + w*8 + k): addr = (w*8+k)*32 + (lane ^ w) -> distinct banks
    #pragma unroll
    for (int k = 0; k < 8; k++)
        r[k] = sh[(w * 8 + k) * 32 + (lane ^ w)];

    // bits 8-12 (strides 256..4096): idx bit (8+s) == lane bit s -> shfl.xor
    #pragma unroll
    for (int m = 1; m <= 16; m <<= 1) {
        const float sgn = (lane & m) ? -1.0f : 1.0f;
        #pragma unroll
        for (int k = 0; k < 8; k++) {
            float o = __shfl_xor_sync(0xffffffffu, r[k], m);
            r[k] = fmaf(sgn, r[k], o);
        }
    }

    // Scale and write out: thread owns idx = lane*256 + w*8 + k (8 contiguous)
    {
        const float s10  = s1[0];
        const int  obase = lane * 256 + w * 8;
        float sa[8];
        *(float4*)&sa[0] = *(const float4*)(s2 + obase);
        *(float4*)&sa[4] = *(const float4*)(s2 + obase + 4);
        float o[8];
        #pragma unroll
        for (int k = 0; k < 8; k++) o[k] = s10 * sa[k] * r[k];
        *(float4*)(d_w + obase)     = *(float4*)&o[0];
        *(float4*)(d_w + obase + 4) = *(float4*)&o[4];
    }
}

// ---------------------------------------------------------------------------
// Kernel 2: out[b][j] = x[b] * w[j]   (128 MiB streaming store)
// Persistent: grid (8, 148), 256 thr, forced 8 blocks/SM -> exactly one wave.
// Each block owns a 1024-float column chunk; grid-strides over 4-row groups.
// PDL: preload x into smem BEFORE cudaGridDependencySynchronize() so the
// prologue overlaps the fwht kernel's tail + launch latency.
// ---------------------------------------------------------------------------
__global__ __launch_bounds__(256, 8)
void outer_kernel(const float* __restrict__ x, float* __restrict__ out) {
    __shared__ float xs[32];
    const int tid = threadIdx.x;

    // Preload this block's x values (independent of kernel 1's output).
    if (tid < 32) {
        int i = tid >> 2;                 // row-group iteration 0..7
        int q = tid & 3;                  // row within group
        int g = blockIdx.y + i * 148;
        xs[tid] = (g < BATCH / 4) ? __ldg(x + g * 4 + q) : 0.0f;
    }

#if __CUDA_ARCH__ >= 900
    cudaGridDependencySynchronize();      // wait for fwht_kernel's d_w
#endif
    __syncthreads();

    const int jbase = blockIdx.x * 1024 + tid * 4;
    const float4 w4 = *(const float4*)(d_w + jbase);

    int it = 0;
    for (int g = blockIdx.y; g < BATCH / 4; g += 148, ++it) {
        float4* p = (float4*)(out + (size_t)g * 4 * D + jbase);
        #pragma unroll
        for (int q = 0; q < 4; q++) {
            float xv = xs[it * 4 + q];
            float4 o = make_float4(xv * w4.x, xv * w4.y, xv * w4.z, xv * w4.w);
            // Streaming store: 134 MB output, never re-read -> evict-first.
            __stcs(p + (size_t)q * (D / 4), o);
        }
    }
}

extern "C" void kernel_launch(void* const* d_in, const int* in_sizes, int n_in,
                              void* d_out, int out_size) {
    const float* x     = (const float*)d_in[0];  // (4096, 1)
    const float* s1    = (const float*)d_in[1];  // (8192,)
    const float* s2    = (const float*)d_in[2];  // (8192,)
    const float* g_mu  = (const float*)d_in[3];  // (8192,)
    const float* g_rho = (const float*)d_in[4];  // (8192,)
    const float* eps   = (const float*)d_in[5];  // (8192,)
    float* out = (float*)d_out;                  // (4096, 8192) f32

    fwht_kernel<<<1, 1024>>>(s1, s2, g_mu, g_rho, eps);

    // Dependent launch with PDL so its prologue overlaps kernel 1.
    cudaLaunchConfig_t cfg = {};
    cfg.gridDim  = dim3(D / 1024, 148, 1);   // (8, 148) persistent
    cfg.blockDim = dim3(256, 1, 1);
    cfg.stream   = 0;
    cudaLaunchAttribute attr;
    attr.id = cudaLaunchAttributeProgrammaticStreamSerialization;
    attr.val.programmaticStreamSerializationAllowed = 1;
    cfg.attrs    = &attr;
    cfg.numAttrs = 1;
    cudaLaunchKernelEx(&cfg, outer_kernel, x, out);
}

// round 3
// speedup vs baseline: 1.1888x; 1.1661x over previous
#include <cuda_runtime.h>
#include <cuda_bf16.h>

#define D 8192
#define BATCH 4096

// Intermediate z = s1[0] * (H_64 (x) I_128) g_tilde  (high-bit FWHT stages done).
__device__ float d_z[D];

// ---------------------------------------------------------------------------
// Kernel 1: high-bit stages (strides 128,256,...,4096) = 128 independent
// 64-point FWHTs over index sets {g*128 + low : g=0..63}, one warp per low.
// 16 blocks x 256 threads (128 warps). lane = g bits 0..4 (shfl), g bit 5 local.
// Also folds in g_tilde = g_mu + softplus(g_rho)*eps and the s1[0] scale.
// ---------------------------------------------------------------------------
__global__ __launch_bounds__(256, 1)
void stageA_kernel(const float* __restrict__ s1,
                   const float* __restrict__ g_mu,
                   const float* __restrict__ g_rho,
                   const float* __restrict__ eps) {
#if __CUDA_ARCH__ >= 900
    cudaTriggerProgrammaticLaunchCompletion();   // let outer's prologue start now
#endif
    const int lane = threadIdx.x & 31;
    const int wi   = threadIdx.x >> 5;
    const int low  = blockIdx.x * 8 + wi;        // 0..127
    const float s10 = __ldg(s1);

    const int e0 = lane * 128 + low;             // g = lane
    const int e1 = e0 + 32 * 128;                // g = lane + 32

    float r0, r1;
    {
        float v0 = __ldg(g_rho + e0), v1 = __ldg(g_rho + e1);
        float sp0 = fmaxf(v0, 0.0f) + __logf(1.0f + __expf(-fabsf(v0)));
        float sp1 = fmaxf(v1, 0.0f) + __logf(1.0f + __expf(-fabsf(v1)));
        r0 = s10 * fmaf(sp0, __ldg(eps + e0), __ldg(g_mu + e0));
        r1 = s10 * fmaf(sp1, __ldg(eps + e1), __ldg(g_mu + e1));
    }

    // g bits 0..4 via shfl.xor (strides 128..2048)
    #pragma unroll
    for (int m = 1; m <= 16; m <<= 1) {
        const float sgn = (lane & m) ? -1.0f : 1.0f;
        float o0 = __shfl_xor_sync(0xffffffffu, r0, m);
        float o1 = __shfl_xor_sync(0xffffffffu, r1, m);
        r0 = fmaf(sgn, r0, o0);
        r1 = fmaf(sgn, r1, o1);
    }
    // g bit 5 (stride 4096): local butterfly
    float a = r0, b = r1;
    d_z[e0] = a + b;
    d_z[e1] = a - b;
}

// ---------------------------------------------------------------------------
// Kernel 2: finish low-bit FWHT stages (strides 1..64, confined to 128-groups)
// on this block's 1024-column chunk, apply s2, then stream the rank-1 outer
// product: out[b][j] = x[b] * w[j].   grid (8, 256), 256 threads, 16 rows/blk.
// PDL: x and s2 are preloaded BEFORE the grid dependency sync.
// ---------------------------------------------------------------------------
#define ROWS_PER_BLOCK 16

__global__ __launch_bounds__(256)
void outer_kernel(const float* __restrict__ x,
                  const float* __restrict__ s2,
                  float* __restrict__ out) {
    __shared__ float sw[1024];
    const int tid  = threadIdx.x;
    const int lane = tid & 31;
    const int r    = tid >> 5;                    // warp = 128-group within chunk
    const int jb   = blockIdx.x * 1024;
    const int base = jb + r * 128 + lane;         // elems base + k*32, k=0..3
    const int b0   = blockIdx.y * ROWS_PER_BLOCK;

    // ---- prologue independent of kernel 1 ----
    float xs[ROWS_PER_BLOCK];
    #pragma unroll
    for (int q = 0; q < ROWS_PER_BLOCK; q++)
        xs[q] = __ldg(x + b0 + q);                // broadcast loads

    float s2v[4];
    #pragma unroll
    for (int k = 0; k < 4; k++)
        s2v[k] = __ldg(s2 + base + k * 32);

#if __CUDA_ARCH__ >= 900
    cudaGridDependencySynchronize();              // wait for d_z
#endif

    // ---- load z chunk: low bits: lane = bits 0..4, k = bits 5..6 ----
    float rr[4];
    #pragma unroll
    for (int k = 0; k < 4; k++)
        rr[k] = d_z[base + k * 32];

    // strides 1..16 via shfl.xor on lane bits
    #pragma unroll
    for (int m = 1; m <= 16; m <<= 1) {
        const float sgn = (lane & m) ? -1.0f : 1.0f;
        #pragma unroll
        for (int k = 0; k < 4; k++) {
            float o = __shfl_xor_sync(0xffffffffu, rr[k], m);
            rr[k] = fmaf(sgn, rr[k], o);
        }
    }
    // stride 32 (k bit 0): (0,1), (2,3)
    {
        float a0 = rr[0], b0_ = rr[1], a1 = rr[2], b1 = rr[3];
        rr[0] = a0 + b0_; rr[1] = a0 - b0_;
        rr[2] = a1 + b1;  rr[3] = a1 - b1;
    }
    // stride 64 (k bit 1): (0,2), (1,3)
    {
        float a0 = rr[0], b0_ = rr[2], a1 = rr[1], b1 = rr[3];
        rr[0] = a0 + b0_; rr[2] = a0 - b0_;
        rr[1] = a1 + b1;  rr[3] = a1 - b1;
    }

    // apply s2 and transpose through smem so each thread owns 4 contiguous cols
    #pragma unroll
    for (int k = 0; k < 4; k++)
        sw[r * 128 + k * 32 + lane] = s2v[k] * rr[k];
    __syncthreads();

    const float4 w4 = *(const float4*)&sw[tid * 4];
    const int jbase = jb + tid * 4;

    #pragma unroll
    for (int q = 0; q < ROWS_PER_BLOCK; q++) {
        float xv = xs[q];
        float4 o = make_float4(xv * w4.x, xv * w4.y, xv * w4.z, xv * w4.w);
        // 134 MB output, never re-read -> streaming (evict-first) store
        __stcs((float4*)(out + (size_t)(b0 + q) * D + jbase), o);
    }
}

extern "C" void kernel_launch(void* const* d_in, const int* in_sizes, int n_in,
                              void* d_out, int out_size) {
    const float* x     = (const float*)d_in[0];  // (4096, 1)
    const float* s1    = (const float*)d_in[1];  // (8192,)
    const float* s2    = (const float*)d_in[2];  // (8192,)
    const float* g_mu  = (const float*)d_in[3];  // (8192,)
    const float* g_rho = (const float*)d_in[4];  // (8192,)
    const float* eps   = (const float*)d_in[5];  // (8192,)
    float* out = (float*)d_out;                  // (4096, 8192) f32

    stageA_kernel<<<16, 256>>>(s1, g_mu, g_rho, eps);

    cudaLaunchConfig_t cfg = {};
    cfg.gridDim  = dim3(D / 1024, BATCH / ROWS_PER_BLOCK, 1);  // (8, 256)
    cfg.blockDim = dim3(256, 1, 1);
    cfg.stream   = 0;
    cudaLaunchAttribute attr;
    attr.id = cudaLaunchAttributeProgrammaticStreamSerialization;
    attr.val.programmaticStreamSerializationAllowed = 1;
    cfg.attrs    = &attr;
    cfg.numAttrs = 1;
    cudaLaunchKernelEx(&cfg, outer_kernel, x, s2, out);
}